// round 1
// baseline (speedup 1.0000x reference)
#include <cuda_runtime.h>
#include <cstdint>

#define NUM_BINS 31
#define THREADS 256
#define WARPS (THREADS / 32)
#define GRID 1184   // 148 SMs * 8 blocks

// ---------------- device-global accumulators (reset every launch) ----------
__device__ unsigned int       g_min_key;
__device__ unsigned int       g_max_key;
__device__ double             g_sum;
__device__ double             g_ss;
__device__ unsigned long long g_nnz;
__device__ int                g_counts[NUM_BINS];

// Order-preserving float <-> uint key (total order incl. negatives)
__device__ __forceinline__ unsigned int fkey(float f) {
    unsigned int b = __float_as_uint(f);
    return b ^ ((b & 0x80000000u) ? 0xFFFFFFFFu : 0x80000000u);
}
__device__ __forceinline__ float funkey(unsigned int k) {
    unsigned int b = (k & 0x80000000u) ? (k ^ 0x80000000u) : ~k;
    return __uint_as_float(b);
}

// ---------------------------------------------------------------------------
__global__ void reset_kernel() {
    if (threadIdx.x == 0) {
        g_min_key = 0xFFFFFFFFu;
        g_max_key = 0u;
        g_sum = 0.0;
        g_ss  = 0.0;
        g_nnz = 0ull;
    }
    if (threadIdx.x < NUM_BINS) g_counts[threadIdx.x] = 0;
}

// ---------------------------------------------------------------------------
// Pass 1: min / max / sum / sumsq / nnz
__global__ void __launch_bounds__(THREADS)
reduce_kernel(const float4* __restrict__ x4, int n4) {
    float mn =  __int_as_float(0x7F800000);   // +inf
    float mx = -__int_as_float(0x7F800000);   // -inf
    float s  = 0.f;
    float ss = 0.f;
    int   nz = 0;

    int stride = gridDim.x * blockDim.x;
    for (int i = blockIdx.x * blockDim.x + threadIdx.x; i < n4; i += stride) {
        float4 v = x4[i];
        mn = fminf(mn, fminf(fminf(v.x, v.y), fminf(v.z, v.w)));
        mx = fmaxf(mx, fmaxf(fmaxf(v.x, v.y), fmaxf(v.z, v.w)));
        s += v.x; s += v.y; s += v.z; s += v.w;
        ss = fmaf(v.x, v.x, ss);
        ss = fmaf(v.y, v.y, ss);
        ss = fmaf(v.z, v.z, ss);
        ss = fmaf(v.w, v.w, ss);
        nz += (v.x != 0.f) + (v.y != 0.f) + (v.z != 0.f) + (v.w != 0.f);
    }

    // warp reduce
    #pragma unroll
    for (int o = 16; o > 0; o >>= 1) {
        mn = fminf(mn, __shfl_xor_sync(0xFFFFFFFFu, mn, o));
        mx = fmaxf(mx, __shfl_xor_sync(0xFFFFFFFFu, mx, o));
        s  += __shfl_xor_sync(0xFFFFFFFFu, s,  o);
        ss += __shfl_xor_sync(0xFFFFFFFFu, ss, o);
        nz += __shfl_xor_sync(0xFFFFFFFFu, nz, o);
    }

    __shared__ float  sh_mn[WARPS], sh_mx[WARPS];
    __shared__ double sh_s[WARPS],  sh_ss[WARPS];
    __shared__ int    sh_nz[WARPS];
    int lane = threadIdx.x & 31;
    int wid  = threadIdx.x >> 5;
    if (lane == 0) {
        sh_mn[wid] = mn; sh_mx[wid] = mx;
        sh_s[wid]  = (double)s; sh_ss[wid] = (double)ss;
        sh_nz[wid] = nz;
    }
    __syncthreads();
    if (wid == 0) {
        mn = (lane < WARPS) ? sh_mn[lane] :  __int_as_float(0x7F800000);
        mx = (lane < WARPS) ? sh_mx[lane] : -__int_as_float(0x7F800000);
        double ds  = (lane < WARPS) ? sh_s[lane]  : 0.0;
        double dss = (lane < WARPS) ? sh_ss[lane] : 0.0;
        nz = (lane < WARPS) ? sh_nz[lane] : 0;
        #pragma unroll
        for (int o = 4; o > 0; o >>= 1) {
            mn = fminf(mn, __shfl_xor_sync(0xFFFFFFFFu, mn, o));
            mx = fmaxf(mx, __shfl_xor_sync(0xFFFFFFFFu, mx, o));
            ds  += __shfl_xor_sync(0xFFFFFFFFu, ds,  o);
            dss += __shfl_xor_sync(0xFFFFFFFFu, dss, o);
            nz  += __shfl_xor_sync(0xFFFFFFFFu, nz,  o);
        }
        if (lane == 0) {
            atomicMin(&g_min_key, fkey(mn));
            atomicMax(&g_max_key, fkey(mx));
            atomicAdd(&g_sum, ds);
            atomicAdd(&g_ss,  dss);
            atomicAdd(&g_nnz, (unsigned long long)nz);
        }
    }
}

// ---------------------------------------------------------------------------
// Pass 2: histogram with searchsorted(side="right") semantics, last bin
// right-inclusive. Per-warp privatized shared histograms (padded rows).
__global__ void __launch_bounds__(THREADS)
hist_kernel(const float4* __restrict__ x4, int n4) {
    __shared__ float s_edges[NUM_BINS + 1];
    __shared__ int   s_hist[WARPS][NUM_BINS + 2];   // pad to 33 -> conflict-free

    float mn = funkey(g_min_key);
    float mx = funkey(g_max_key);
    float step = (mx - mn) / (float)NUM_BINS;

    if (threadIdx.x <= NUM_BINS) {
        float e = mn + (float)threadIdx.x * step;
        if (threadIdx.x == NUM_BINS) e = mx;
        s_edges[threadIdx.x] = e;
    }
    for (int i = threadIdx.x; i < WARPS * (NUM_BINS + 2); i += blockDim.x)
        ((int*)s_hist)[i] = 0;
    __syncthreads();

    float inv = (float)NUM_BINS / (mx - mn);
    int w = threadIdx.x >> 5;
    int stride = gridDim.x * blockDim.x;

    for (int i = blockIdx.x * blockDim.x + threadIdx.x; i < n4; i += stride) {
        float4 v = x4[i];
        #pragma unroll
        for (int c = 0; c < 4; c++) {
            float val = (c == 0) ? v.x : (c == 1) ? v.y : (c == 2) ? v.z : v.w;
            int idx = (int)((val - mn) * inv);
            idx = max(0, min(idx, NUM_BINS - 1));
            // correct against exact output edges (searchsorted right semantics)
            while (idx < NUM_BINS - 1 && val >= s_edges[idx + 1]) idx++;
            while (idx > 0 && val < s_edges[idx]) idx--;
            atomicAdd(&s_hist[w][idx], 1);
        }
    }
    __syncthreads();

    for (int b = threadIdx.x; b < NUM_BINS; b += blockDim.x) {
        int t = 0;
        #pragma unroll
        for (int ww = 0; ww < WARPS; ww++) t += s_hist[ww][b];
        atomicAdd(&g_counts[b], t);
    }
}

// ---------------------------------------------------------------------------
// Output layout (float32): [mn, mx, num, nnz, sum, sumsq, counts[31], edges[32]]
__global__ void finalize_kernel(float* __restrict__ out, int n) {
    float mn = funkey(g_min_key);
    float mx = funkey(g_max_key);
    int t = threadIdx.x;
    if (t == 0) {
        out[0] = mn;
        out[1] = mx;
        out[2] = (float)n;
        out[3] = (float)g_nnz;
        out[4] = (float)g_sum;
        out[5] = (float)g_ss;
    }
    if (t < NUM_BINS) out[6 + t] = (float)g_counts[t];
    if (t <= NUM_BINS) {
        float e = mn + (float)t * ((mx - mn) / (float)NUM_BINS);
        if (t == NUM_BINS) e = mx;
        out[6 + NUM_BINS + t] = e;
    }
}

// ---------------------------------------------------------------------------
extern "C" void kernel_launch(void* const* d_in, const int* in_sizes, int n_in,
                              void* d_out, int out_size) {
    const float* x = (const float*)d_in[0];
    int n  = in_sizes[0];
    int n4 = n / 4;   // N = 64M, divisible by 4
    float* out = (float*)d_out;

    reset_kernel<<<1, 64>>>();
    reduce_kernel<<<GRID, THREADS>>>((const float4*)x, n4);
    hist_kernel  <<<GRID, THREADS>>>((const float4*)x, n4);
    finalize_kernel<<<1, 64>>>(out, n);
}